// round 3
// baseline (speedup 1.0000x reference)
#include <cuda_runtime.h>
#include <cuda_bf16.h>

// out_j = (sum_k (Offset_k*4 + mean_k) * s_k * r[j][k] + T_j*300) / 280
// with s = (S, -S, S) * 20,  r = Rx(pi*Rx)·Ry(pi*Ry)·Rz(pi*Rz).
// Folded per batch into A[j][k] = s_k*r[j][k]/280 and t_j = T_j*300/280.

#define PI_F 3.14159265358979323846f

// Per-batch folded params: 16 floats per batch (9 matrix, 3 bias, 4 pad).
// __device__ global scratch (no cudaMalloc allowed). Supports B up to 4096.
__device__ float g_params[4096 * 16];

__global__ void setup_params_kernel(const float* __restrict__ R,
                                    const float* __restrict__ T,
                                    const float* __restrict__ S,
                                    int B) {
    int b = blockIdx.x * blockDim.x + threadIdx.x;
    if (b >= B) return;

    float ax = R[b * 3 + 0] * PI_F;
    float ay = R[b * 3 + 1] * PI_F;
    float az = R[b * 3 + 2] * PI_F;
    float sx, cx, sy, cy, sz, cz;
    sincosf(ax, &sx, &cx);
    sincosf(ay, &sy, &cy);
    sincosf(az, &sz, &cz);

    // r = rx @ ry @ rz  (matching the JAX reference exactly)
    // rx = [[1,0,0],[0,cx,sx],[0,-sx,cx]]
    // ry = [[cy,0,-sy],[0,1,0],[sy,0,cy]]
    // rz = [[cz,sz,0],[-sz,cz,0],[0,0,1]]
    float r00 = cy * cz;
    float r01 = cy * sz;
    float r02 = -sy;
    float r10 = sx * sy * cz - cx * sz;
    float r11 = cx * cz + sx * sy * sz;
    float r12 = sx * cy;
    float r20 = cx * sy * cz + sx * sz;
    float r21 = cx * sy * sz - sx * cz;
    float r22 = cx * cy;

    float Sv = S[b];
    float sc = Sv * (20.0f / 280.0f);   // S_SCALE=20 folded with /280
    float s0 = sc, s1 = -sc, s2 = sc;

    float* p = g_params + b * 16;
    // A[j][k] = s_k * r[j][k] (scale already folded)
    p[0] = r00 * s0;  p[1] = r01 * s1;  p[2] = r02 * s2;
    p[3] = r10 * s0;  p[4] = r11 * s1;  p[5] = r12 * s2;
    p[6] = r20 * s0;  p[7] = r21 * s1;  p[8] = r22 * s2;
    p[9]  = T[b * 3 + 0] * (300.0f / 280.0f);
    p[10] = T[b * 3 + 1] * (300.0f / 280.0f);
    p[11] = T[b * 3 + 2] * (300.0f / 280.0f);
    p[12] = 0.f; p[13] = 0.f; p[14] = 0.f; p[15] = 0.f;
}

#define XFORM_LANE(V0, V1, V2, O0, O1, O2)                                   \
    do {                                                                     \
        O0 = fmaf(V0, A00, fmaf(V1, A01, fmaf(V2, A02, t0)));                \
        O1 = fmaf(V0, A10, fmaf(V1, A11, fmaf(V2, A12, t1)));                \
        O2 = fmaf(V0, A20, fmaf(V1, A21, fmaf(V2, A22, t2)));                \
    } while (0)

// Vectorized streaming kernel: each thread handles ITEMS float4-quads of one
// batch (6 float4 loads + 3 float4 stores per quad, fully coalesced).
template <int ITEMS>
__global__ __launch_bounds__(256)
void transform_kernel(const float4* __restrict__ off,
                      const float4* __restrict__ mean,
                      float4* __restrict__ out,
                      int quads,            // pixels/4 per channel
                      int blocks_per_batch) {
    int b  = blockIdx.x / blocks_per_batch;
    int rb = blockIdx.x - b * blocks_per_batch;
    int q0 = rb * (256 * ITEMS) + threadIdx.x;

    const float* __restrict__ p = g_params + b * 16;
    float A00 = p[0], A01 = p[1], A02 = p[2];
    float A10 = p[3], A11 = p[4], A12 = p[5];
    float A20 = p[6], A21 = p[7], A22 = p[8];
    float t0 = p[9], t1 = p[10], t2 = p[11];

    int cbase = b * 3 * quads;

#pragma unroll
    for (int it = 0; it < ITEMS; ++it) {
        int q = q0 + it * 256;
        float4 o0 = off[cbase + q];
        float4 o1 = off[cbase + quads + q];
        float4 o2 = off[cbase + 2 * quads + q];
        float4 m0 = mean[q];
        float4 m1 = mean[quads + q];
        float4 m2 = mean[2 * quads + q];

        float4 e0, e1, e2;
        {
            float v0 = fmaf(o0.x, 4.f, m0.x);
            float v1 = fmaf(o1.x, 4.f, m1.x);
            float v2 = fmaf(o2.x, 4.f, m2.x);
            XFORM_LANE(v0, v1, v2, e0.x, e1.x, e2.x);
        }
        {
            float v0 = fmaf(o0.y, 4.f, m0.y);
            float v1 = fmaf(o1.y, 4.f, m1.y);
            float v2 = fmaf(o2.y, 4.f, m2.y);
            XFORM_LANE(v0, v1, v2, e0.y, e1.y, e2.y);
        }
        {
            float v0 = fmaf(o0.z, 4.f, m0.z);
            float v1 = fmaf(o1.z, 4.f, m1.z);
            float v2 = fmaf(o2.z, 4.f, m2.z);
            XFORM_LANE(v0, v1, v2, e0.z, e1.z, e2.z);
        }
        {
            float v0 = fmaf(o0.w, 4.f, m0.w);
            float v1 = fmaf(o1.w, 4.f, m1.w);
            float v2 = fmaf(o2.w, 4.f, m2.w);
            XFORM_LANE(v0, v1, v2, e0.w, e1.w, e2.w);
        }

        out[cbase + q]             = e0;
        out[cbase + quads + q]     = e1;
        out[cbase + 2 * quads + q] = e2;
    }
}

// Scalar grid-stride fallback for shapes not divisible by the vector tile.
__global__ __launch_bounds__(256)
void transform_scalar_kernel(const float* __restrict__ off,
                             const float* __restrict__ mean,
                             float* __restrict__ out,
                             int B, int pixels) {
    long total = (long)B * pixels;
    long stride = (long)gridDim.x * blockDim.x;
    for (long i = blockIdx.x * (long)blockDim.x + threadIdx.x; i < total; i += stride) {
        int b = (int)(i / pixels);
        int n = (int)(i - (long)b * pixels);
        const float* __restrict__ p = g_params + b * 16;
        long cb = (long)b * 3 * pixels;
        float v0 = fmaf(off[cb + n],              4.f, mean[n]);
        float v1 = fmaf(off[cb + pixels + n],     4.f, mean[pixels + n]);
        float v2 = fmaf(off[cb + 2 * pixels + n], 4.f, mean[2 * pixels + n]);
        out[cb + n]              = fmaf(v0, p[0], fmaf(v1, p[1], fmaf(v2, p[2], p[9])));
        out[cb + pixels + n]     = fmaf(v0, p[3], fmaf(v1, p[4], fmaf(v2, p[5], p[10])));
        out[cb + 2 * pixels + n] = fmaf(v0, p[6], fmaf(v1, p[7], fmaf(v2, p[8], p[11])));
    }
}

extern "C" void kernel_launch(void* const* d_in, const int* in_sizes, int n_in,
                              void* d_out, int out_size) {
    const float* Offset = (const float*)d_in[0];   // (B, 3, 256, 256)
    const float* R      = (const float*)d_in[1];   // (B, 3)
    const float* T      = (const float*)d_in[2];   // (B, 1, 3)
    const float* S      = (const float*)d_in[3];   // (B, 1)
    const float* mean   = (const float*)d_in[4];   // (3, 256, 256)
    float* out          = (float*)d_out;

    int B      = in_sizes[1] / 3;
    int pixels = in_sizes[4] / 3;   // 65536

    // Stage 1: per-batch folded 3x3 matrix + bias.
    setup_params_kernel<<<(B + 255) / 256, 256>>>(R, T, S, B);

    // Stage 2: streaming transform.
    constexpr int ITEMS = 2;
    if ((pixels % 4) == 0 && ((pixels / 4) % (256 * ITEMS)) == 0) {
        int quads = pixels / 4;
        int blocks_per_batch = quads / (256 * ITEMS);   // 32 for 256x256
        transform_kernel<ITEMS><<<B * blocks_per_batch, 256>>>(
            (const float4*)Offset, (const float4*)mean, (float4*)out,
            quads, blocks_per_batch);
    } else {
        long total = (long)B * pixels;
        int blocks = (int)((total + 255) / 256);
        if (blocks > 65535 * 32) blocks = 65535 * 32;
        transform_scalar_kernel<<<blocks, 256>>>(Offset, mean, out, B, pixels);
    }
}